// round 16
// baseline (speedup 1.0000x reference)
#include <cuda_runtime.h>
#include <cuda_fp16.h>
#include <math.h>
#include <stdint.h>

#define TOTAL 65536
#define DMODEL 512
#define EQKV   1536
#define NGRAPH 1024
#define NPG    64
#define NHEAD  8
#define HD     64
#define PADROW 65

// ------------------------------- scratch ----------------------------------
__device__ float g_qkv[(size_t)TOTAL * EQKV];
__device__ float g_att[(size_t)TOTAL * DMODEL];
__device__ __half g_xh[(size_t)TOTAL * DMODEL];
__device__ __half g_ctxh[(size_t)TOTAL * DMODEL];
__device__ __half g_inwh[(size_t)EQKV * DMODEL];
__device__ __half g_outwh[(size_t)DMODEL * DMODEL];

// ------------------------------ PTX helpers -------------------------------
__device__ __forceinline__ uint32_t smem_u32(const void* p) {
    uint32_t a;
    asm("{ .reg .u64 t; cvta.to.shared.u64 t, %1; cvt.u32.u64 %0, t; }"
        : "=r"(a) : "l"(p));
    return a;
}
#define LDSM_X4(r0, r1, r2, r3, addr) \
    asm volatile("ldmatrix.sync.aligned.m8n8.x4.shared.b16 {%0,%1,%2,%3}, [%4];" \
        : "=r"(r0), "=r"(r1), "=r"(r2), "=r"(r3) : "r"(addr))
#define LDSM_X2(r0, r1, addr) \
    asm volatile("ldmatrix.sync.aligned.m8n8.x2.shared.b16 {%0,%1}, [%2];" \
        : "=r"(r0), "=r"(r1) : "r"(addr))
#define MMA_FP16(d, a, b) \
    asm volatile("mma.sync.aligned.m16n8k16.row.col.f32.f16.f16.f32 " \
        "{%0,%1,%2,%3}, {%4,%5,%6,%7}, {%8,%9}, {%0,%1,%2,%3};" \
        : "+f"((d)[0]), "+f"((d)[1]), "+f"((d)[2]), "+f"((d)[3]) \
        : "r"((a)[0]), "r"((a)[1]), "r"((a)[2]), "r"((a)[3]), \
          "r"((b)[0]), "r"((b)[1]))
#define CP_ASYNC16(dst, src) \
    asm volatile("cp.async.cg.shared.global [%0], [%1], 16;" \
        :: "r"(dst), "l"(src) : "memory")
#define CP_COMMIT() asm volatile("cp.async.commit_group;" ::: "memory")
#define CP_WAIT(n)  asm volatile("cp.async.wait_group %0;" :: "n"(n) : "memory")

// --------------------------- conversion kernel ----------------------------
__global__ void __launch_bounds__(256) cvt_fp16(
    const float* __restrict__ src, __half* __restrict__ dst, size_t n4)
{
    size_t i = (size_t)blockIdx.x * 256 + threadIdx.x;
    if (i >= n4) return;
    float4 v = ((const float4*)src)[i];
    __half2 H0(__float2half(v.x), __float2half(v.y));
    __half2 H1(__float2half(v.z), __float2half(v.w));
    ((uint2*)dst)[i] = make_uint2(*(uint32_t*)&H0, *(uint32_t*)&H1);
}

// ===========================================================================
// 1-pass fp16 mma.sync GEMM: C = A*B^T + bias. 128x128 tile, 8 warps (2x4),
// K-chunk 64 (pitch 144, conflict-free), cp.async double-buffered, 2 CTAs/SM.
// ===========================================================================
#define PITCH64 144
#define TILEB64 (128 * PITCH64)       // 18432 B per matrix
#define BUFB64  (2 * TILEB64)         // Ah, Bh = 36864 B per stage
#define GEMM1P_SMEM (2 * BUFB64)      // 73728 B

__global__ void __launch_bounds__(256, 2) gemm_fp16_1p(
    const __half* __restrict__ Ah,
    const __half* __restrict__ Bh,
    const float* __restrict__ bias, float* __restrict__ C,
    int N, int K)
{
    extern __shared__ __align__(16) uint8_t smem[];
    const uint32_t smBase = smem_u32(smem);

    const int tid  = threadIdx.x;
    const int wid  = tid >> 5;
    const int lane = tid & 31;
    const int wm   = wid >> 2;
    const int wn   = wid & 3;
    const int rowBase = blockIdx.y * 128;
    const int colBase = blockIdx.x * 128;

    // 4 granules (16B) per thread per matrix: 1024 granules = 128 rows x 8
    const int gBase = tid * 4;

    const __half* pAh = Ah + (size_t)rowBase * K;
    const __half* pBh = Bh + (size_t)colBase * K;

    const int NC = K >> 6;   // 64-wide chunks

    auto loadChunk = [&](int c) {
        const int k0 = c << 6;
        const uint32_t bOff = smBase + (c & 1) * BUFB64;
        #pragma unroll
        for (int gi = 0; gi < 4; gi++) {
            const int g  = gBase + gi;
            const int rg = g >> 3;
            const int cg = g & 7;
            const uint32_t d = (uint32_t)(rg * PITCH64 + cg * 16);
            const size_t  s = (size_t)rg * K + k0 + cg * 8;
            CP_ASYNC16(bOff + d, pAh + s);
            CP_ASYNC16(bOff + TILEB64 + d, pBh + s);
        }
    };

    float acc[4][4][4];
    #pragma unroll
    for (int mf = 0; mf < 4; mf++)
        #pragma unroll
        for (int nf = 0; nf < 4; nf++)
            #pragma unroll
            for (int e = 0; e < 4; e++) acc[mf][nf][e] = 0.f;

    loadChunk(0);
    CP_COMMIT();

    for (int c = 0; c < NC; c++) {
        if (c + 1 < NC) {
            loadChunk(c + 1);
            CP_COMMIT();
            CP_WAIT(1);
        } else {
            CP_WAIT(0);
        }
        __syncthreads();

        const uint32_t bOff = smBase + (c & 1) * BUFB64;
        const uint32_t aAh = bOff;
        const uint32_t aBh = bOff + TILEB64;

        #pragma unroll
        for (int ks = 0; ks < 4; ks++) {
            const uint32_t kcol = (uint32_t)ks * 32;
            uint32_t bh[4][2];
            #pragma unroll
            for (int nf = 0; nf < 4; nf++) {
                uint32_t brow = wn * 32 + nf * 8 + (lane & 7);
                uint32_t boff = brow * PITCH64 + kcol + (((uint32_t)lane >> 3) & 1) * 16;
                LDSM_X2(bh[nf][0], bh[nf][1], aBh + boff);
            }
            #pragma unroll
            for (int mf = 0; mf < 4; mf++) {
                uint32_t arow = wm * 64 + mf * 16 + (lane & 15);
                uint32_t aoff = arow * PITCH64 + kcol + ((uint32_t)lane >> 4) * 16;
                uint32_t ah[4];
                LDSM_X4(ah[0], ah[1], ah[2], ah[3], aAh + aoff);
                #pragma unroll
                for (int nf = 0; nf < 4; nf++) {
                    MMA_FP16(acc[mf][nf], ah, bh[nf]);
                }
            }
        }
        __syncthreads();
    }

    const int er = rowBase + wm * 64 + (lane >> 2);
    const int ec = colBase + wn * 32 + (lane & 3) * 2;
    #pragma unroll
    for (int mf = 0; mf < 4; mf++) {
        #pragma unroll
        for (int nf = 0; nf < 4; nf++) {
            int row = er + mf * 16;
            int col = ec + nf * 8;
            float b0 = bias[col], b1 = bias[col + 1];
            *(float2*)&C[(size_t)row * N + col] =
                make_float2(acc[mf][nf][0] + b0, acc[mf][nf][1] + b1);
            *(float2*)&C[(size_t)(row + 8) * N + col] =
                make_float2(acc[mf][nf][2] + b0, acc[mf][nf][3] + b1);
        }
    }
}

// ===========================================================================
// Per (graph, head) attention (R15 version, unchanged)
// ===========================================================================
__global__ void __launch_bounds__(256) attn_kernel()
{
    extern __shared__ float sm[];
    float* Qs = sm;
    float* Ks = sm + 1 * 64 * PADROW;
    float* Vs = sm + 2 * 64 * PADROW;
    float* Ss = sm + 3 * 64 * PADROW;

    int h = blockIdx.x;
    int g = blockIdx.y;
    int tid = threadIdx.x;

    size_t base = (size_t)g * NPG * EQKV + (size_t)h * HD;

    for (int i = tid; i < NPG * HD / 4; i += 256) {
        int n = i >> 4;
        int d = (i & 15) * 4;
        size_t src = base + (size_t)n * EQKV + d;
        float4 q = *(const float4*)&g_qkv[src];
        float4 k = *(const float4*)&g_qkv[src + DMODEL];
        float4 v = *(const float4*)&g_qkv[src + 2 * DMODEL];
        float* qd = &Qs[n * PADROW + d];
        float* kd = &Ks[n * PADROW + d];
        float* vd = &Vs[n * PADROW + d];
        qd[0] = q.x; qd[1] = q.y; qd[2] = q.z; qd[3] = q.w;
        kd[0] = k.x; kd[1] = k.y; kd[2] = k.z; kd[3] = k.w;
        vd[0] = v.x; vd[1] = v.y; vd[2] = v.z; vd[3] = v.w;
    }
    __syncthreads();

    int tx = tid & 15, ty = tid >> 4;
    int n0 = ty * 4, m0 = tx * 4;

    {
        float c[4][4];
        #pragma unroll
        for (int i = 0; i < 4; i++)
            #pragma unroll
            for (int j = 0; j < 4; j++) c[i][j] = 0.f;
        for (int d = 0; d < HD; d++) {
            float a[4], b[4];
            #pragma unroll
            for (int i = 0; i < 4; i++) a[i] = Qs[(n0 + i) * PADROW + d];
            #pragma unroll
            for (int j = 0; j < 4; j++) b[j] = Ks[(m0 + j) * PADROW + d];
            #pragma unroll
            for (int i = 0; i < 4; i++)
                #pragma unroll
                for (int j = 0; j < 4; j++)
                    c[i][j] = fmaf(a[i], b[j], c[i][j]);
        }
        #pragma unroll
        for (int i = 0; i < 4; i++)
            #pragma unroll
            for (int j = 0; j < 4; j++)
                Ss[(n0 + i) * PADROW + m0 + j] = c[i][j] * 0.125f;
    }
    __syncthreads();

    {
        int warp = tid >> 5, lane = tid & 31;
        for (int r = 0; r < 8; r++) {
            int n = warp * 8 + r;
            float v0 = Ss[n * PADROW + lane];
            float v1 = Ss[n * PADROW + lane + 32];
            float mx = fmaxf(v0, v1);
            #pragma unroll
            for (int o = 16; o > 0; o >>= 1)
                mx = fmaxf(mx, __shfl_xor_sync(0xffffffffu, mx, o));
            float e0 = __expf(v0 - mx);
            float e1 = __expf(v1 - mx);
            float s = e0 + e1;
            #pragma unroll
            for (int o = 16; o > 0; o >>= 1)
                s += __shfl_xor_sync(0xffffffffu, s, o);
            float inv = 1.f / s;
            Ss[n * PADROW + lane]      = e0 * inv;
            Ss[n * PADROW + lane + 32] = e1 * inv;
        }
    }
    __syncthreads();

    {
        float c[4][4];
        #pragma unroll
        for (int i = 0; i < 4; i++)
            #pragma unroll
            for (int j = 0; j < 4; j++) c[i][j] = 0.f;
        for (int m = 0; m < NPG; m++) {
            float a[4], b[4];
            #pragma unroll
            for (int i = 0; i < 4; i++) a[i] = Ss[(n0 + i) * PADROW + m];
            #pragma unroll
            for (int j = 0; j < 4; j++) b[j] = Vs[m * PADROW + m0 + j];
            #pragma unroll
            for (int i = 0; i < 4; i++)
                #pragma unroll
                for (int j = 0; j < 4; j++)
                    c[i][j] = fmaf(a[i], b[j], c[i][j]);
        }
        #pragma unroll
        for (int i = 0; i < 4; i++) {
            size_t row = (size_t)(g * NPG + n0 + i) * DMODEL + h * HD + m0;
            __half2 h01(__float2half(c[i][0]), __float2half(c[i][1]));
            __half2 h23(__float2half(c[i][2]), __float2half(c[i][3]));
            *(__half2*)&g_ctxh[row]     = h01;
            *(__half2*)&g_ctxh[row + 2] = h23;
        }
    }
}

// ===========================================================================
// Per-graph gate + reduction
// ===========================================================================
__global__ void __launch_bounds__(256) gate_reduce(
    const float* __restrict__ gw, const float* __restrict__ gb,
    float* __restrict__ out)
{
    __shared__ float gates[NPG];
    int g = blockIdx.x;
    const float* base = g_att + (size_t)g * NPG * DMODEL;

    int warp = threadIdx.x >> 5, lane = threadIdx.x & 31;
    for (int r = 0; r < 8; r++) {
        int n = warp * 8 + r;
        const float* row = base + (size_t)n * DMODEL;
        float s = 0.f;
        #pragma unroll
        for (int c = 0; c < DMODEL / 32; c++)
            s = fmaf(row[lane + c * 32], gw[lane + c * 32], s);
        #pragma unroll
        for (int o = 16; o > 0; o >>= 1)
            s += __shfl_xor_sync(0xffffffffu, s, o);
        if (lane == 0)
            gates[n] = 1.f / (1.f + __expf(-(s + gb[0])));
    }
    __syncthreads();

    for (int c = threadIdx.x; c < DMODEL; c += 256) {
        float acc = 0.f;
        #pragma unroll 8
        for (int n = 0; n < NPG; n++)
            acc = fmaf(gates[n], base[(size_t)n * DMODEL + c], acc);
        out[(size_t)g * DMODEL + c] = acc;
    }
}

// ===========================================================================
extern "C" void kernel_launch(void* const* d_in, const int* in_sizes, int n_in,
                              void* d_out, int out_size)
{
    const float* x      = (const float*)d_in[0];
    const float* in_w   = (const float*)d_in[2];
    const float* in_b   = (const float*)d_in[3];
    const float* out_w  = (const float*)d_in[4];
    const float* out_b  = (const float*)d_in[5];
    const float* gate_w = (const float*)d_in[6];
    const float* gate_b = (const float*)d_in[7];
    float* out          = (float*)d_out;

    float *qkv, *att;
    __half *xh, *ctxh, *inwh, *outwh;
    cudaGetSymbolAddress((void**)&qkv, g_qkv);
    cudaGetSymbolAddress((void**)&att, g_att);
    cudaGetSymbolAddress((void**)&xh, g_xh);
    cudaGetSymbolAddress((void**)&ctxh, g_ctxh);
    cudaGetSymbolAddress((void**)&inwh, g_inwh);
    cudaGetSymbolAddress((void**)&outwh, g_outwh);

    const int smem_attn = 4 * 64 * PADROW * sizeof(float);
    cudaFuncSetAttribute(attn_kernel,
                         cudaFuncAttributeMaxDynamicSharedMemorySize, smem_attn);
    cudaFuncSetAttribute(gemm_fp16_1p,
                         cudaFuncAttributeMaxDynamicSharedMemorySize, GEMM1P_SMEM);

    // 0) operand conversion (all fp16-hi only)
    {
        size_t n4 = (size_t)TOTAL * DMODEL / 4;
        cvt_fp16<<<(unsigned)((n4 + 255) / 256), 256>>>(x, xh, n4);
        size_t w4 = (size_t)EQKV * DMODEL / 4;
        cvt_fp16<<<(unsigned)((w4 + 255) / 256), 256>>>(in_w, inwh, w4);
        size_t o4 = (size_t)DMODEL * DMODEL / 4;
        cvt_fp16<<<(unsigned)((o4 + 255) / 256), 256>>>(out_w, outwh, o4);
    }

    // 1) QKV projection (1-pass fp16, K-chunk 64)
    gemm_fp16_1p<<<dim3(EQKV / 128, TOTAL / 128), 256, GEMM1P_SMEM>>>(
        xh, inwh, in_b, qkv, EQKV, DMODEL);

    // 2) attention (fp32, emits ctx fp16 hi only)
    attn_kernel<<<dim3(NHEAD, NGRAPH), 256, smem_attn>>>();

    // 3) output projection (1-pass fp16, K-chunk 64)
    gemm_fp16_1p<<<dim3(DMODEL / 128, TOTAL / 128), 256, GEMM1P_SMEM>>>(
        ctxh, outwh, out_b, att, DMODEL, DMODEL);

    // 4) gate + per-graph reduction
    gate_reduce<<<NGRAPH, 256>>>(gate_w, gate_b, out);
}

// round 17
// speedup vs baseline: 1.0223x; 1.0223x over previous
#include <cuda_runtime.h>
#include <cuda_fp16.h>
#include <math.h>
#include <stdint.h>

#define TOTAL 65536
#define DMODEL 512
#define EQKV   1536
#define NGRAPH 1024
#define NPG    64
#define NHEAD  8
#define HD     64
#define PADROW 65

// ------------------------------- scratch ----------------------------------
__device__ __half g_qkvh[(size_t)TOTAL * EQKV];
__device__ float g_att[(size_t)TOTAL * DMODEL];
__device__ __half g_xh[(size_t)TOTAL * DMODEL];
__device__ __half g_ctxh[(size_t)TOTAL * DMODEL];
__device__ __half g_inwh[(size_t)EQKV * DMODEL];
__device__ __half g_outwh[(size_t)DMODEL * DMODEL];

// ------------------------------ PTX helpers -------------------------------
__device__ __forceinline__ uint32_t smem_u32(const void* p) {
    uint32_t a;
    asm("{ .reg .u64 t; cvta.to.shared.u64 t, %1; cvt.u32.u64 %0, t; }"
        : "=r"(a) : "l"(p));
    return a;
}
#define LDSM_X4(r0, r1, r2, r3, addr) \
    asm volatile("ldmatrix.sync.aligned.m8n8.x4.shared.b16 {%0,%1,%2,%3}, [%4];" \
        : "=r"(r0), "=r"(r1), "=r"(r2), "=r"(r3) : "r"(addr))
#define LDSM_X2(r0, r1, addr) \
    asm volatile("ldmatrix.sync.aligned.m8n8.x2.shared.b16 {%0,%1}, [%2];" \
        : "=r"(r0), "=r"(r1) : "r"(addr))
#define MMA_FP16(d, a, b) \
    asm volatile("mma.sync.aligned.m16n8k16.row.col.f32.f16.f16.f32 " \
        "{%0,%1,%2,%3}, {%4,%5,%6,%7}, {%8,%9}, {%0,%1,%2,%3};" \
        : "+f"((d)[0]), "+f"((d)[1]), "+f"((d)[2]), "+f"((d)[3]) \
        : "r"((a)[0]), "r"((a)[1]), "r"((a)[2]), "r"((a)[3]), \
          "r"((b)[0]), "r"((b)[1]))
#define CP_ASYNC16(dst, src) \
    asm volatile("cp.async.cg.shared.global [%0], [%1], 16;" \
        :: "r"(dst), "l"(src) : "memory")
#define CP_COMMIT() asm volatile("cp.async.commit_group;" ::: "memory")
#define CP_WAIT(n)  asm volatile("cp.async.wait_group %0;" :: "n"(n) : "memory")

// --------------------------- conversion kernel ----------------------------
__global__ void __launch_bounds__(256) cvt_fp16(
    const float* __restrict__ src, __half* __restrict__ dst, size_t n4)
{
    size_t i = (size_t)blockIdx.x * 256 + threadIdx.x;
    if (i >= n4) return;
    float4 v = ((const float4*)src)[i];
    __half2 H0(__float2half(v.x), __float2half(v.y));
    __half2 H1(__float2half(v.z), __float2half(v.w));
    ((uint2*)dst)[i] = make_uint2(*(uint32_t*)&H0, *(uint32_t*)&H1);
}

// ===========================================================================
// 1-pass fp16 mma.sync GEMM core (R15 config: K-chunk 32, pitch 80, 2 CTA/SM)
// Two epilogue variants: fp32 out (+bias) and fp16 out (+bias).
// ===========================================================================
#define PITCH 80
#define TILEB (128 * PITCH)
#define BUFB1 (2 * TILEB)           // Ah, Bh = 20480 B per stage
#define GEMM1P_SMEM (2 * BUFB1)     // 40960 B

#define GEMM_PROLOG_AND_MAINLOOP                                               \
    extern __shared__ __align__(16) uint8_t smem[];                            \
    const uint32_t smBase = smem_u32(smem);                                    \
    const int tid  = threadIdx.x;                                              \
    const int wid  = tid >> 5;                                                 \
    const int lane = tid & 31;                                                 \
    const int wm   = wid >> 2;                                                 \
    const int wn   = wid & 3;                                                  \
    const int rowBase = blockIdx.y * 128;                                      \
    const int colBase = blockIdx.x * 128;                                      \
    const int g0 = tid * 2;                                                    \
    const int r0g = g0 >> 2, c0g = g0 & 3;                                     \
    const int g1 = tid * 2 + 1;                                                \
    const int r1g = g1 >> 2, c1g = g1 & 3;                                     \
    const __half* pAh = Ah + (size_t)rowBase * K;                              \
    const __half* pBh = Bh + (size_t)colBase * K;                              \
    const int NC = K >> 5;                                                     \
    auto loadChunk = [&](int c) {                                              \
        const int k0 = c << 5;                                                 \
        const uint32_t bOff = smBase + (c & 1) * BUFB1;                        \
        const uint32_t d0 = (uint32_t)(r0g * PITCH + c0g * 16);                \
        const uint32_t d1 = (uint32_t)(r1g * PITCH + c1g * 16);                \
        const size_t s0 = (size_t)r0g * K + k0 + c0g * 8;                      \
        const size_t s1 = (size_t)r1g * K + k0 + c1g * 8;                      \
        CP_ASYNC16(bOff + 0 * TILEB + d0, pAh + s0);                           \
        CP_ASYNC16(bOff + 0 * TILEB + d1, pAh + s1);                           \
        CP_ASYNC16(bOff + 1 * TILEB + d0, pBh + s0);                           \
        CP_ASYNC16(bOff + 1 * TILEB + d1, pBh + s1);                           \
    };                                                                         \
    float acc[4][4][4];                                                        \
    _Pragma("unroll")                                                          \
    for (int mf = 0; mf < 4; mf++)                                             \
        _Pragma("unroll")                                                      \
        for (int nf = 0; nf < 4; nf++)                                         \
            _Pragma("unroll")                                                  \
            for (int e = 0; e < 4; e++) acc[mf][nf][e] = 0.f;                  \
    loadChunk(0);                                                              \
    CP_COMMIT();                                                               \
    for (int c = 0; c < NC; c++) {                                             \
        if (c + 1 < NC) { loadChunk(c + 1); CP_COMMIT(); CP_WAIT(1); }         \
        else            { CP_WAIT(0); }                                        \
        __syncthreads();                                                       \
        const uint32_t bOff = smBase + (c & 1) * BUFB1;                        \
        const uint32_t aAh = bOff;                                             \
        const uint32_t aBh = bOff + 1 * TILEB;                                 \
        _Pragma("unroll")                                                      \
        for (int ks = 0; ks < 2; ks++) {                                       \
            const uint32_t kcol = (uint32_t)ks * 32;                           \
            uint32_t bh[4][2];                                                 \
            _Pragma("unroll")                                                  \
            for (int nf = 0; nf < 4; nf++) {                                   \
                uint32_t brow = wn * 32 + nf * 8 + (lane & 7);                 \
                uint32_t boff = brow * PITCH + kcol + (((uint32_t)lane >> 3) & 1) * 16; \
                LDSM_X2(bh[nf][0], bh[nf][1], aBh + boff);                     \
            }                                                                  \
            _Pragma("unroll")                                                  \
            for (int mf = 0; mf < 4; mf++) {                                   \
                uint32_t arow = wm * 64 + mf * 16 + (lane & 15);               \
                uint32_t aoff = arow * PITCH + kcol + ((uint32_t)lane >> 4) * 16; \
                uint32_t ah[4];                                                \
                LDSM_X4(ah[0], ah[1], ah[2], ah[3], aAh + aoff);               \
                _Pragma("unroll")                                              \
                for (int nf = 0; nf < 4; nf++) {                               \
                    MMA_FP16(acc[mf][nf], ah, bh[nf]);                         \
                }                                                              \
            }                                                                  \
        }                                                                      \
        __syncthreads();                                                       \
    }                                                                          \
    const int er = rowBase + wm * 64 + (lane >> 2);                            \
    const int ec = colBase + wn * 32 + (lane & 3) * 2;

// fp32 output epilogue
__global__ void __launch_bounds__(256, 2) gemm_fp16_1p(
    const __half* __restrict__ Ah,
    const __half* __restrict__ Bh,
    const float* __restrict__ bias, float* __restrict__ C,
    int N, int K)
{
    GEMM_PROLOG_AND_MAINLOOP
    #pragma unroll
    for (int mf = 0; mf < 4; mf++) {
        #pragma unroll
        for (int nf = 0; nf < 4; nf++) {
            int row = er + mf * 16;
            int col = ec + nf * 8;
            float b0 = bias[col], b1 = bias[col + 1];
            *(float2*)&C[(size_t)row * N + col] =
                make_float2(acc[mf][nf][0] + b0, acc[mf][nf][1] + b1);
            *(float2*)&C[(size_t)(row + 8) * N + col] =
                make_float2(acc[mf][nf][2] + b0, acc[mf][nf][3] + b1);
        }
    }
}

// fp16 output epilogue (for qkv)
__global__ void __launch_bounds__(256, 2) gemm_fp16_1p_h(
    const __half* __restrict__ Ah,
    const __half* __restrict__ Bh,
    const float* __restrict__ bias, __half* __restrict__ C,
    int N, int K)
{
    GEMM_PROLOG_AND_MAINLOOP
    #pragma unroll
    for (int mf = 0; mf < 4; mf++) {
        #pragma unroll
        for (int nf = 0; nf < 4; nf++) {
            int row = er + mf * 16;
            int col = ec + nf * 8;
            float b0 = bias[col], b1 = bias[col + 1];
            __half2 o0(__float2half(acc[mf][nf][0] + b0),
                       __float2half(acc[mf][nf][1] + b1));
            __half2 o1(__float2half(acc[mf][nf][2] + b0),
                       __float2half(acc[mf][nf][3] + b1));
            *(__half2*)&C[(size_t)row * N + col]       = o0;
            *(__half2*)&C[(size_t)(row + 8) * N + col] = o1;
        }
    }
}

// ===========================================================================
// Per (graph, head) attention: loads fp16 qkv, computes fp32, ctx fp16 out
// ===========================================================================
__global__ void __launch_bounds__(256) attn_kernel()
{
    extern __shared__ float sm[];
    float* Qs = sm;
    float* Ks = sm + 1 * 64 * PADROW;
    float* Vs = sm + 2 * 64 * PADROW;
    float* Ss = sm + 3 * 64 * PADROW;

    int h = blockIdx.x;
    int g = blockIdx.y;
    int tid = threadIdx.x;

    size_t base = (size_t)g * NPG * EQKV + (size_t)h * HD;

    // 8 halves (16 B) per thread per matrix per iter; 512 vec-iters total
    for (int i = tid; i < NPG * HD / 8; i += 256) {
        int n = i >> 3;
        int d = (i & 7) * 8;
        size_t src = base + (size_t)n * EQKV + d;
        uint4 qv = *(const uint4*)&g_qkvh[src];
        uint4 kv = *(const uint4*)&g_qkvh[src + DMODEL];
        uint4 vv = *(const uint4*)&g_qkvh[src + 2 * DMODEL];

        float2 q0 = __half22float2(*(__half2*)&qv.x);
        float2 q1 = __half22float2(*(__half2*)&qv.y);
        float2 q2 = __half22float2(*(__half2*)&qv.z);
        float2 q3 = __half22float2(*(__half2*)&qv.w);
        float2 k0 = __half22float2(*(__half2*)&kv.x);
        float2 k1 = __half22float2(*(__half2*)&kv.y);
        float2 k2 = __half22float2(*(__half2*)&kv.z);
        float2 k3 = __half22float2(*(__half2*)&kv.w);
        float2 v0 = __half22float2(*(__half2*)&vv.x);
        float2 v1 = __half22float2(*(__half2*)&vv.y);
        float2 v2 = __half22float2(*(__half2*)&vv.z);
        float2 v3 = __half22float2(*(__half2*)&vv.w);

        float* qd = &Qs[n * PADROW + d];
        float* kd = &Ks[n * PADROW + d];
        float* vd = &Vs[n * PADROW + d];
        qd[0] = q0.x; qd[1] = q0.y; qd[2] = q1.x; qd[3] = q1.y;
        qd[4] = q2.x; qd[5] = q2.y; qd[6] = q3.x; qd[7] = q3.y;
        kd[0] = k0.x; kd[1] = k0.y; kd[2] = k1.x; kd[3] = k1.y;
        kd[4] = k2.x; kd[5] = k2.y; kd[6] = k3.x; kd[7] = k3.y;
        vd[0] = v0.x; vd[1] = v0.y; vd[2] = v1.x; vd[3] = v1.y;
        vd[4] = v2.x; vd[5] = v2.y; vd[6] = v3.x; vd[7] = v3.y;
    }
    __syncthreads();

    int tx = tid & 15, ty = tid >> 4;
    int n0 = ty * 4, m0 = tx * 4;

    {
        float c[4][4];
        #pragma unroll
        for (int i = 0; i < 4; i++)
            #pragma unroll
            for (int j = 0; j < 4; j++) c[i][j] = 0.f;
        for (int d = 0; d < HD; d++) {
            float a[4], b[4];
            #pragma unroll
            for (int i = 0; i < 4; i++) a[i] = Qs[(n0 + i) * PADROW + d];
            #pragma unroll
            for (int j = 0; j < 4; j++) b[j] = Ks[(m0 + j) * PADROW + d];
            #pragma unroll
            for (int i = 0; i < 4; i++)
                #pragma unroll
                for (int j = 0; j < 4; j++)
                    c[i][j] = fmaf(a[i], b[j], c[i][j]);
        }
        #pragma unroll
        for (int i = 0; i < 4; i++)
            #pragma unroll
            for (int j = 0; j < 4; j++)
                Ss[(n0 + i) * PADROW + m0 + j] = c[i][j] * 0.125f;
    }
    __syncthreads();

    {
        int warp = tid >> 5, lane = tid & 31;
        for (int r = 0; r < 8; r++) {
            int n = warp * 8 + r;
            float v0 = Ss[n * PADROW + lane];
            float v1 = Ss[n * PADROW + lane + 32];
            float mx = fmaxf(v0, v1);
            #pragma unroll
            for (int o = 16; o > 0; o >>= 1)
                mx = fmaxf(mx, __shfl_xor_sync(0xffffffffu, mx, o));
            float e0 = __expf(v0 - mx);
            float e1 = __expf(v1 - mx);
            float s = e0 + e1;
            #pragma unroll
            for (int o = 16; o > 0; o >>= 1)
                s += __shfl_xor_sync(0xffffffffu, s, o);
            float inv = 1.f / s;
            Ss[n * PADROW + lane]      = e0 * inv;
            Ss[n * PADROW + lane + 32] = e1 * inv;
        }
    }
    __syncthreads();

    {
        float c[4][4];
        #pragma unroll
        for (int i = 0; i < 4; i++)
            #pragma unroll
            for (int j = 0; j < 4; j++) c[i][j] = 0.f;
        for (int m = 0; m < NPG; m++) {
            float a[4], b[4];
            #pragma unroll
            for (int i = 0; i < 4; i++) a[i] = Ss[(n0 + i) * PADROW + m];
            #pragma unroll
            for (int j = 0; j < 4; j++) b[j] = Vs[m * PADROW + m0 + j];
            #pragma unroll
            for (int i = 0; i < 4; i++)
                #pragma unroll
                for (int j = 0; j < 4; j++)
                    c[i][j] = fmaf(a[i], b[j], c[i][j]);
        }
        #pragma unroll
        for (int i = 0; i < 4; i++) {
            size_t row = (size_t)(g * NPG + n0 + i) * DMODEL + h * HD + m0;
            __half2 h01(__float2half(c[i][0]), __float2half(c[i][1]));
            __half2 h23(__float2half(c[i][2]), __float2half(c[i][3]));
            *(__half2*)&g_ctxh[row]     = h01;
            *(__half2*)&g_ctxh[row + 2] = h23;
        }
    }
}

// ===========================================================================
// Per-graph gate + reduction
// ===========================================================================
__global__ void __launch_bounds__(256) gate_reduce(
    const float* __restrict__ gw, const float* __restrict__ gb,
    float* __restrict__ out)
{
    __shared__ float gates[NPG];
    int g = blockIdx.x;
    const float* base = g_att + (size_t)g * NPG * DMODEL;

    int warp = threadIdx.x >> 5, lane = threadIdx.x & 31;
    for (int r = 0; r < 8; r++) {
        int n = warp * 8 + r;
        const float* row = base + (size_t)n * DMODEL;
        float s = 0.f;
        #pragma unroll
        for (int c = 0; c < DMODEL / 32; c++)
            s = fmaf(row[lane + c * 32], gw[lane + c * 32], s);
        #pragma unroll
        for (int o = 16; o > 0; o >>= 1)
            s += __shfl_xor_sync(0xffffffffu, s, o);
        if (lane == 0)
            gates[n] = 1.f / (1.f + __expf(-(s + gb[0])));
    }
    __syncthreads();

    for (int c = threadIdx.x; c < DMODEL; c += 256) {
        float acc = 0.f;
        #pragma unroll 8
        for (int n = 0; n < NPG; n++)
            acc = fmaf(gates[n], base[(size_t)n * DMODEL + c], acc);
        out[(size_t)g * DMODEL + c] = acc;
    }
}

// ===========================================================================
extern "C" void kernel_launch(void* const* d_in, const int* in_sizes, int n_in,
                              void* d_out, int out_size)
{
    const float* x      = (const float*)d_in[0];
    const float* in_w   = (const float*)d_in[2];
    const float* in_b   = (const float*)d_in[3];
    const float* out_w  = (const float*)d_in[4];
    const float* out_b  = (const float*)d_in[5];
    const float* gate_w = (const float*)d_in[6];
    const float* gate_b = (const float*)d_in[7];
    float* out          = (float*)d_out;

    float *att;
    __half *qkvh, *xh, *ctxh, *inwh, *outwh;
    cudaGetSymbolAddress((void**)&qkvh, g_qkvh);
    cudaGetSymbolAddress((void**)&att, g_att);
    cudaGetSymbolAddress((void**)&xh, g_xh);
    cudaGetSymbolAddress((void**)&ctxh, g_ctxh);
    cudaGetSymbolAddress((void**)&inwh, g_inwh);
    cudaGetSymbolAddress((void**)&outwh, g_outwh);

    const int smem_attn = 4 * 64 * PADROW * sizeof(float);
    cudaFuncSetAttribute(attn_kernel,
                         cudaFuncAttributeMaxDynamicSharedMemorySize, smem_attn);
    cudaFuncSetAttribute(gemm_fp16_1p,
                         cudaFuncAttributeMaxDynamicSharedMemorySize, GEMM1P_SMEM);
    cudaFuncSetAttribute(gemm_fp16_1p_h,
                         cudaFuncAttributeMaxDynamicSharedMemorySize, GEMM1P_SMEM);

    // 0) operand conversion (all fp16-hi only)
    {
        size_t n4 = (size_t)TOTAL * DMODEL / 4;
        cvt_fp16<<<(unsigned)((n4 + 255) / 256), 256>>>(x, xh, n4);
        size_t w4 = (size_t)EQKV * DMODEL / 4;
        cvt_fp16<<<(unsigned)((w4 + 255) / 256), 256>>>(in_w, inwh, w4);
        size_t o4 = (size_t)DMODEL * DMODEL / 4;
        cvt_fp16<<<(unsigned)((o4 + 255) / 256), 256>>>(out_w, outwh, o4);
    }

    // 1) QKV projection (1-pass fp16, fp16 output)
    gemm_fp16_1p_h<<<dim3(EQKV / 128, TOTAL / 128), 256, GEMM1P_SMEM>>>(
        xh, inwh, in_b, qkvh, EQKV, DMODEL);

    // 2) attention (fp16 in, fp32 compute, fp16 ctx out)
    attn_kernel<<<dim3(NHEAD, NGRAPH), 256, smem_attn>>>();

    // 3) output projection (1-pass fp16, fp32 output)
    gemm_fp16_1p<<<dim3(DMODEL / 128, TOTAL / 128), 256, GEMM1P_SMEM>>>(
        ctxh, outwh, out_b, att, DMODEL, DMODEL);

    // 4) gate + per-graph reduction
    gate_reduce<<<NGRAPH, 256>>>(gate_w, gate_b, out);
}